// round 14
// baseline (speedup 1.0000x reference)
#include <cuda_runtime.h>
#include <cuda_bf16.h>
#include <cstdint>
#include <math.h>

// Problem dims
#define B_ 2
#define T_ 256
#define N_ 128
#define F_ 16
#define D_ 128
#define H_ 288
#define E_ 1024
#define M_TOTAL (B_*T_*N_)

typedef uint32_t u32;

// Scratch (allocation-free)
__device__ float g_S1[(size_t)M_TOTAL * H_];
__device__ float g_R1[(size_t)M_TOTAL * H_];
__device__ float g_pet2[2][256 * H_];     // [0]=petS(t), [1]=petR(t)+bc1
__device__ int   g_se_s[E_], g_re_s[E_], g_perm[E_];

// Fragment-ordered split-bf16 weight image, hi/lo interleaved per uint4:
//   g_Wfi[chain][pos] = {bh0, bh1, bl0, bl1} for fragment (kt, j, lane)
// Offsets in uint4 units.
#define OFF_EMB 0          // kt=1, NJ=16 -> 512
#define OFF_W1  512        // kt=8, NJ=16 -> 4096
#define OFF_W2  4608       // kt=8, NJ=16 -> 4096
#define OFF_WC  8704       // 3 chunks, each kt=8, NJ=12 -> 3072
#define WFI_TOTAL 17920
__device__ uint4 g_Wfi[2][WFI_TOTAL];

// ---------------- helpers ---------------------------------------------------
__device__ __forceinline__ u32 bpack(__nv_bfloat16 a, __nv_bfloat16 b) {
    return ((u32)__bfloat16_as_ushort(b) << 16) | (u32)__bfloat16_as_ushort(a);
}
__device__ __forceinline__ u32 split_pack(float v0, float v1, u32& lo) {
    __nv_bfloat16 h0 = __float2bfloat16(v0);
    __nv_bfloat16 h1 = __float2bfloat16(v1);
    lo = bpack(__float2bfloat16(v0 - __bfloat162float(h0)),
               __float2bfloat16(v1 - __bfloat162float(h1)));
    return bpack(h0, h1);
}
__device__ __forceinline__ void mma16816(float* d, const u32* a, u32 b0, u32 b1) {
    asm volatile(
        "mma.sync.aligned.m16n8k16.row.col.f32.bf16.bf16.f32 "
        "{%0,%1,%2,%3}, {%4,%5,%6,%7}, {%8,%9}, {%0,%1,%2,%3};"
        : "+f"(d[0]), "+f"(d[1]), "+f"(d[2]), "+f"(d[3])
        : "r"(a[0]), "r"(a[1]), "r"(a[2]), "r"(a[3]), "r"(b0), "r"(b1));
}

// ---------------------------------------------------------------------------
// prep_wf: pack weights into interleaved uint4 fragment image.
// B-frag (m16n8k16, col): lane(g=lane>>2, tg=lane&3), reg r in {0,1}:
//   elements (k, n), (k+1, n) with k = kt*16 + r*8 + 2*tg, n = coff + 8*j + g.
// ---------------------------------------------------------------------------
__global__ void prep_wf(const float* __restrict__ W_emb,
                        const float* __restrict__ Ws1, const float* __restrict__ Ws2,
                        const float* __restrict__ Wr1, const float* __restrict__ Wr2,
                        const float* __restrict__ Wc1)
{
    const int chain = blockIdx.y;
    int pos = blockIdx.x * 256 + threadIdx.x;
    if (pos >= WFI_TOTAL) return;

    const float* W; int rel, NJ, N = 128, koff = 0, coff = 0;
    if (pos < OFF_W1)      { rel = pos;          NJ = 16; W = W_emb; }
    else if (pos < OFF_W2) { rel = pos - OFF_W1; NJ = 16; W = chain ? Wr1 : Ws1; }
    else if (pos < OFF_WC) { rel = pos - OFF_W2; NJ = 16; W = chain ? Wr2 : Ws2; }
    else {
        int rel2 = pos - OFF_WC;
        int c = rel2 / 3072; rel = rel2 % 3072;
        NJ = 12; W = Wc1; N = 288; koff = chain ? 144 : 0; coff = 96 * c;
    }
    int lane = rel & 31;
    int t    = rel >> 5;
    int j    = t % NJ;
    int kt   = t / NJ;
    int gg   = lane >> 2;
    int tg   = lane & 3;
    int n    = coff + 8 * j + gg;

    uint4 w;
    {
        int k = kt * 16 + 2 * tg;                 // r = 0
        float v0 = W[(size_t)(k + koff) * N + n];
        float v1 = W[(size_t)(k + 1 + koff) * N + n];
        w.x = split_pack(v0, v1, w.z);
    }
    {
        int k = kt * 16 + 8 + 2 * tg;             // r = 1
        float v0 = W[(size_t)(k + koff) * N + n];
        float v1 = W[(size_t)(k + 1 + koff) * N + n];
        w.y = split_pack(v0, v1, w.w);
    }
    g_Wfi[chain][pos] = w;
}

// ---------------------------------------------------------------------------
// pet2_kernel (unchanged)
// ---------------------------------------------------------------------------
__global__ void pet2_kernel(const float* __restrict__ Wc1,
                            const float* __restrict__ bc1)
{
    const int t = blockIdx.x;       // 0..255
    const int c = threadIdx.x;      // 0..287

    __shared__ float sv[2][8];
    if (c < 8) {
        double dv = exp((double)(2 * c) * (-log(10000.0) / 16.0));
        double a = (double)t * dv;
        sv[0][c] = (float)sin(a);
        sv[1][c] = (float)cos(a);
    }
    __syncthreads();

    float accS = 0.f, accR = bc1[c];
    #pragma unroll
    for (int i = 0; i < 8; i++) {
        accS = fmaf(sv[0][i], Wc1[(128 + 2 * i) * H_ + c], accS);
        accS = fmaf(sv[1][i], Wc1[(129 + 2 * i) * H_ + c], accS);
        accR = fmaf(sv[0][i], Wc1[(272 + 2 * i) * H_ + c], accR);
        accR = fmaf(sv[1][i], Wc1[(273 + 2 * i) * H_ + c], accR);
    }
    g_pet2[0][t * H_ + c] = accS;
    g_pet2[1][t * H_ + c] = accR;
}

// ---------------------------------------------------------------------------
// sort_edges (unchanged)
// ---------------------------------------------------------------------------
__global__ void sort_edges(const int* __restrict__ se, const int* __restrict__ re)
{
    __shared__ int cnt[129];
    __shared__ int cur[128];
    const int tid = threadIdx.x;    // 256 threads
    if (tid < 129) cnt[tid] = 0;
    __syncthreads();
    for (int e = tid; e < E_; e += 256) atomicAdd(&cnt[se[e] + 1], 1);
    __syncthreads();
    if (tid == 0)
        for (int i = 1; i <= 128; i++) cnt[i] += cnt[i - 1];
    __syncthreads();
    if (tid < 128) cur[tid] = cnt[tid];
    __syncthreads();
    for (int e = tid; e < E_; e += 256) {
        int s = se[e];
        int pos = atomicAdd(&cur[s], 1);
        g_se_s[pos] = s;
        g_re_s[pos] = re[e];
        g_perm[pos] = e;
    }
}

// ---------------------------------------------------------------------------
// layer128_s: full unroll, Al frags in SMEM, interleaved uint4 weight loads.
// sAl layout: sAl[kt*512 + tid*4 + q]
// ---------------------------------------------------------------------------
__device__ __forceinline__ void layer128_s(float d[16][4],
                                           u32 Ah[8][4], u32* sAl,
                                           const uint4* __restrict__ Wp,
                                           const float* __restrict__ bias,
                                           int lane, int tig, int tid)
{
    #pragma unroll
    for (int j = 0; j < 16; j++) { d[j][0]=0.f; d[j][1]=0.f; d[j][2]=0.f; d[j][3]=0.f; }
    #pragma unroll
    for (int kt = 0; kt < 8; kt++) {
        uint4 alv = *(const uint4*)(sAl + kt * 512 + tid * 4);
        u32 Al[4] = {alv.x, alv.y, alv.z, alv.w};
        #pragma unroll
        for (int j = 0; j < 16; j++) {
            uint4 w = __ldg(Wp + (kt * 16 + j) * 32 + lane);
            mma16816(d[j], Ah[kt], w.x, w.y);
            mma16816(d[j], Al,     w.x, w.y);
            mma16816(d[j], Ah[kt], w.z, w.w);
        }
    }
    #pragma unroll
    for (int kt = 0; kt < 8; kt++) {
        float2 bA = *(const float2*)(bias + kt * 16 + 2 * tig);
        float2 bB = *(const float2*)(bias + kt * 16 + 8 + 2 * tig);
        float p0 = fmaxf(d[2*kt][0] + bA.x, 0.f), p1 = fmaxf(d[2*kt][1] + bA.y, 0.f);
        float p2 = fmaxf(d[2*kt][2] + bA.x, 0.f), p3 = fmaxf(d[2*kt][3] + bA.y, 0.f);
        float q0 = fmaxf(d[2*kt+1][0] + bB.x, 0.f), q1 = fmaxf(d[2*kt+1][1] + bB.y, 0.f);
        float q2 = fmaxf(d[2*kt+1][2] + bB.x, 0.f), q3 = fmaxf(d[2*kt+1][3] + bB.y, 0.f);
        uint4 alv;
        Ah[kt][0] = split_pack(p0, p1, alv.x);
        Ah[kt][1] = split_pack(p2, p3, alv.y);
        Ah[kt][2] = split_pack(q0, q1, alv.z);
        Ah[kt][3] = split_pack(q2, q3, alv.w);
        *(uint4*)(sAl + kt * 512 + tid * 4) = alv;
    }
}

// ---------------------------------------------------------------------------
// chain_mma: register-resident chain, Al in smem, 3 CTAs/SM, uint4 weights.
// ---------------------------------------------------------------------------
__global__ __launch_bounds__(128, 3)
void chain_mma(const float* __restrict__ spikes,
               const float* __restrict__ b_emb,
               const float* __restrict__ bs1, const float* __restrict__ bs2,
               const float* __restrict__ br1, const float* __restrict__ br2)
{
    __shared__ u32 sAl[8 * 512];    // [kt][tid][q] thread-private Al frags, 16KB

    const int chain = blockIdx.y;
    const int lane  = threadIdx.x & 31;
    const int g     = lane >> 2;
    const int tig   = lane & 3;
    const int tid   = threadIdx.x;
    const int r0    = blockIdx.x * 64 + (tid >> 5) * 16 + g;

    const uint4* Wfi = g_Wfi[chain];
    const float* b1 = chain ? br1 : bs1;
    const float* b2 = chain ? br2 : bs2;
    float* Out = chain ? g_R1 : g_S1;
    const float* padd = g_pet2[chain] + ((r0 >> 7) & 255) * H_;

    u32 Ah[8][4];
    float d[16][4];

    // ---- Layer 0: emb = spikes @ W_emb + b_emb (K=16, 1 k-tile) ----------
    {
        const float* sp = spikes + (size_t)r0 * F_;
        float2 v0 = *(const float2*)(sp + 2 * tig);
        float2 v1 = *(const float2*)(sp + 8 * F_ + 2 * tig);
        float2 v2 = *(const float2*)(sp + 2 * tig + 8);
        float2 v3 = *(const float2*)(sp + 8 * F_ + 2 * tig + 8);
        u32 a0h[4], a0l[4];
        a0h[0] = split_pack(v0.x, v0.y, a0l[0]);
        a0h[1] = split_pack(v1.x, v1.y, a0l[1]);
        a0h[2] = split_pack(v2.x, v2.y, a0l[2]);
        a0h[3] = split_pack(v3.x, v3.y, a0l[3]);

        #pragma unroll
        for (int j = 0; j < 16; j++) { d[j][0]=0.f; d[j][1]=0.f; d[j][2]=0.f; d[j][3]=0.f; }
        const uint4* wp = Wfi + OFF_EMB;
        #pragma unroll
        for (int j = 0; j < 16; j++) {
            uint4 w = __ldg(wp + j * 32 + lane);
            mma16816(d[j], a0h, w.x, w.y);
            mma16816(d[j], a0l, w.x, w.y);
            mma16816(d[j], a0h, w.z, w.w);
        }
        #pragma unroll
        for (int kt = 0; kt < 8; kt++) {
            float2 bA = *(const float2*)(b_emb + kt * 16 + 2 * tig);
            float2 bB = *(const float2*)(b_emb + kt * 16 + 8 + 2 * tig);
            float p0 = d[2*kt][0] + bA.x, p1 = d[2*kt][1] + bA.y;
            float p2 = d[2*kt][2] + bA.x, p3 = d[2*kt][3] + bA.y;
            float q0 = d[2*kt+1][0] + bB.x, q1 = d[2*kt+1][1] + bB.y;
            float q2 = d[2*kt+1][2] + bB.x, q3 = d[2*kt+1][3] + bB.y;
            uint4 alv;
            Ah[kt][0] = split_pack(p0, p1, alv.x);
            Ah[kt][1] = split_pack(p2, p3, alv.y);
            Ah[kt][2] = split_pack(q0, q1, alv.z);
            Ah[kt][3] = split_pack(q2, q3, alv.w);
            *(uint4*)(sAl + kt * 512 + tid * 4) = alv;
        }
    }

    layer128_s(d, Ah, sAl, Wfi + OFF_W1, b1, lane, tig, tid);
    layer128_s(d, Ah, sAl, Wfi + OFF_W2, b2, lane, tig, tid);

    // ---- Layer 3: Out = s @ Wc (N=288, 3 chunks of 96) ---------------------
    #pragma unroll 1
    for (int c = 0; c < 3; c++) {
        float d2[12][4];
        #pragma unroll
        for (int j = 0; j < 12; j++) { d2[j][0]=0.f; d2[j][1]=0.f; d2[j][2]=0.f; d2[j][3]=0.f; }
        const uint4* wp = Wfi + OFF_WC + c * 3072;
        #pragma unroll
        for (int kt = 0; kt < 8; kt++) {
            uint4 alv = *(const uint4*)(sAl + kt * 512 + tid * 4);
            u32 Al[4] = {alv.x, alv.y, alv.z, alv.w};
            #pragma unroll
            for (int j = 0; j < 12; j++) {
                uint4 w = __ldg(wp + (kt * 12 + j) * 32 + lane);
                mma16816(d2[j], Ah[kt], w.x, w.y);
                mma16816(d2[j], Al,     w.x, w.y);
                mma16816(d2[j], Ah[kt], w.z, w.w);
            }
        }
        #pragma unroll
        for (int j = 0; j < 12; j++) {
            int col = c * 96 + j * 8 + 2 * tig;
            float2 pv = *(const float2*)(padd + col);
            *(float2*)(Out + (size_t)r0 * H_ + col) =
                make_float2(d2[j][0] + pv.x, d2[j][1] + pv.y);
            *(float2*)(Out + (size_t)(r0 + 8) * H_ + col) =
                make_float2(d2[j][2] + pv.x, d2[j][3] + pv.y);
        }
    }
}

// ---------------------------------------------------------------------------
// edge_kernel v3 (unchanged — sorted edges, pet folded)
// ---------------------------------------------------------------------------
__global__ __launch_bounds__(256)
void edge_kernel(const float* __restrict__ Wc2, const float* __restrict__ bc2,
                 float* __restrict__ out)
{
    __shared__ float sS[128][33];
    __shared__ float sR[128][33];
    __shared__ float sW[H_ * 5];

    const int t   = blockIdx.x;     // 0..254
    const int b   = blockIdx.y;     // 0..1
    const int tid = threadIdx.x;

    const float* Srow = g_S1 + (size_t)((b * T_ + t + 1) * N_) * H_;
    const float* Rrow = g_R1 + (size_t)((b * T_ + t) * N_) * H_;

    for (int l = tid; l < H_ * 5; l += 256) sW[l] = Wc2[l];

    float bb[5];
    #pragma unroll
    for (int j = 0; j < 5; j++) bb[j] = __ldg(bc2 + j);

    int es[4], er[4], eo[4];
    #pragma unroll
    for (int u = 0; u < 4; u++) {
        int e = u * 256 + tid;
        es[u] = g_se_s[e];
        er[u] = g_re_s[e];
        eo[u] = g_perm[e];
    }
    float acc[4][5] = {};

    #pragma unroll 1
    for (int kc = 0; kc < H_; kc += 32) {
        __syncthreads();
        #pragma unroll
        for (int it = 0; it < 4; it++) {
            int l  = tid + it * 256;
            int n  = l >> 3;
            int k4 = (l & 7) * 4;
            float4 v = *reinterpret_cast<const float4*>(Srow + (size_t)n * H_ + kc + k4);
            sS[n][k4 + 0] = v.x; sS[n][k4 + 1] = v.y;
            sS[n][k4 + 2] = v.z; sS[n][k4 + 3] = v.w;
            float4 u4 = *reinterpret_cast<const float4*>(Rrow + (size_t)n * H_ + kc + k4);
            sR[n][k4 + 0] = u4.x; sR[n][k4 + 1] = u4.y;
            sR[n][k4 + 2] = u4.z; sR[n][k4 + 3] = u4.w;
        }
        __syncthreads();
        #pragma unroll
        for (int kk = 0; kk < 32; kk++) {
            float w0 = sW[(kc + kk) * 5 + 0];
            float w1 = sW[(kc + kk) * 5 + 1];
            float w2 = sW[(kc + kk) * 5 + 2];
            float w3 = sW[(kc + kk) * 5 + 3];
            float w4 = sW[(kc + kk) * 5 + 4];
            #pragma unroll
            for (int u = 0; u < 4; u++) {
                float h = sS[es[u]][kk] + sR[er[u]][kk];
                h = fmaxf(h, 0.f);
                acc[u][0] = fmaf(h, w0, acc[u][0]);
                acc[u][1] = fmaf(h, w1, acc[u][1]);
                acc[u][2] = fmaf(h, w2, acc[u][2]);
                acc[u][3] = fmaf(h, w3, acc[u][3]);
                acc[u][4] = fmaf(h, w4, acc[u][4]);
            }
        }
    }

    #pragma unroll
    for (int u = 0; u < 4; u++) {
        size_t o = ((size_t)(b * 255 + t) * E_ + eo[u]) * 5;
        #pragma unroll
        for (int j = 0; j < 5; j++) out[o + j] = acc[u][j] + bb[j];
    }
}

// ---------------------------------------------------------------------------
extern "C" void kernel_launch(void* const* d_in, const int* in_sizes, int n_in,
                              void* d_out, int out_size)
{
    const float* spikes = (const float*)d_in[0];
    const float* W_emb  = (const float*)d_in[1];
    const float* b_emb  = (const float*)d_in[2];
    const float* Ws1    = (const float*)d_in[3];
    const float* bs1    = (const float*)d_in[4];
    const float* Ws2    = (const float*)d_in[5];
    const float* bs2    = (const float*)d_in[6];
    const float* Wr1    = (const float*)d_in[7];
    const float* br1    = (const float*)d_in[8];
    const float* Wr2    = (const float*)d_in[9];
    const float* br2    = (const float*)d_in[10];
    const float* Wc1    = (const float*)d_in[11];
    const float* bc1    = (const float*)d_in[12];
    const float* Wc2    = (const float*)d_in[13];
    const float* bc2    = (const float*)d_in[14];
    const int*   se     = (const int*)d_in[15];
    const int*   re     = (const int*)d_in[16];
    float* out = (float*)d_out;

    prep_wf<<<dim3((WFI_TOTAL + 255) / 256, 2), 256>>>(
        W_emb, Ws1, Ws2, Wr1, Wr2, Wc1);

    pet2_kernel<<<256, H_>>>(Wc1, bc1);

    sort_edges<<<1, 256>>>(se, re);

    chain_mma<<<dim3(M_TOTAL / 64, 2), 128>>>(
        spikes, b_emb, bs1, bs2, br1, br2);

    edge_kernel<<<dim3(255, 2), 256>>>(Wc2, bc2, out);
}

// round 15
// speedup vs baseline: 1.1520x; 1.1520x over previous
#include <cuda_runtime.h>
#include <cuda_fp16.h>
#include <cstdint>
#include <math.h>

// Problem dims
#define B_ 2
#define T_ 256
#define N_ 128
#define F_ 16
#define D_ 128
#define H_ 288
#define E_ 1024
#define M_TOTAL (B_*T_*N_)

typedef uint32_t u32;

// Scratch (allocation-free)
__device__ float g_S1[(size_t)M_TOTAL * H_];
__device__ float g_R1[(size_t)M_TOTAL * H_];
__device__ float g_pet2[2][256 * H_];     // [0]=petS(t), [1]=petR(t)+bc1
__device__ int   g_se_s[E_], g_re_s[E_], g_perm[E_];

// Fragment-ordered fp16 weight image (hi only; A carries the 2-way split).
//   g_Wfh[chain][pos] = {r0 pair, r1 pair} for fragment (kt, j, lane)
// Offsets in uint2 units.
#define OFF_EMB 0          // kt=1, NJ=16 -> 512
#define OFF_W1  512        // kt=8, NJ=16 -> 4096
#define OFF_W2  4608       // kt=8, NJ=16 -> 4096
#define OFF_WC  8704       // 3 chunks, each kt=8, NJ=12 -> 3072
#define WF_TOTAL 17920
__device__ uint2 g_Wfh[2][WF_TOTAL];

// ---------------- helpers ---------------------------------------------------
__device__ __forceinline__ u32 pack2h(__half a, __half b) {
    return ((u32)__half_as_ushort(b) << 16) | (u32)__half_as_ushort(a);
}
// fp16 2-way split: returns hi pair, writes lo pair (residuals).
__device__ __forceinline__ u32 split_packh(float v0, float v1, u32& lo) {
    __half h0 = __float2half_rn(v0);
    __half h1 = __float2half_rn(v1);
    lo = pack2h(__float2half_rn(v0 - __half2float(h0)),
                __float2half_rn(v1 - __half2float(h1)));
    return pack2h(h0, h1);
}
__device__ __forceinline__ void mma16816(float* d, const u32* a, u32 b0, u32 b1) {
    asm volatile(
        "mma.sync.aligned.m16n8k16.row.col.f32.f16.f16.f32 "
        "{%0,%1,%2,%3}, {%4,%5,%6,%7}, {%8,%9}, {%0,%1,%2,%3};"
        : "+f"(d[0]), "+f"(d[1]), "+f"(d[2]), "+f"(d[3])
        : "r"(a[0]), "r"(a[1]), "r"(a[2]), "r"(a[3]), "r"(b0), "r"(b1));
}

// ---------------------------------------------------------------------------
// prep_wf: pack weights (fp16 hi only) into fragment-ordered uint2 image.
// B-frag (m16n8k16, col): lane(g=lane>>2, tg=lane&3), reg r in {0,1}:
//   elements (k, n), (k+1, n) with k = kt*16 + r*8 + 2*tg, n = coff + 8*j + g.
// ---------------------------------------------------------------------------
__global__ void prep_wf(const float* __restrict__ W_emb,
                        const float* __restrict__ Ws1, const float* __restrict__ Ws2,
                        const float* __restrict__ Wr1, const float* __restrict__ Wr2,
                        const float* __restrict__ Wc1)
{
    const int chain = blockIdx.y;
    int pos = blockIdx.x * 256 + threadIdx.x;
    if (pos >= WF_TOTAL) return;

    const float* W; int rel, NJ, N = 128, koff = 0, coff = 0;
    if (pos < OFF_W1)      { rel = pos;          NJ = 16; W = W_emb; }
    else if (pos < OFF_W2) { rel = pos - OFF_W1; NJ = 16; W = chain ? Wr1 : Ws1; }
    else if (pos < OFF_WC) { rel = pos - OFF_W2; NJ = 16; W = chain ? Wr2 : Ws2; }
    else {
        int rel2 = pos - OFF_WC;
        int c = rel2 / 3072; rel = rel2 % 3072;
        NJ = 12; W = Wc1; N = 288; koff = chain ? 144 : 0; coff = 96 * c;
    }
    int lane = rel & 31;
    int t    = rel >> 5;
    int j    = t % NJ;
    int kt   = t / NJ;
    int gg   = lane >> 2;
    int tg   = lane & 3;
    int n    = coff + 8 * j + gg;

    uint2 w;
    {
        int k = kt * 16 + 2 * tg;                 // r = 0
        w.x = pack2h(__float2half_rn(W[(size_t)(k + koff) * N + n]),
                     __float2half_rn(W[(size_t)(k + 1 + koff) * N + n]));
    }
    {
        int k = kt * 16 + 8 + 2 * tg;             // r = 1
        w.y = pack2h(__float2half_rn(W[(size_t)(k + koff) * N + n]),
                     __float2half_rn(W[(size_t)(k + 1 + koff) * N + n]));
    }
    g_Wfh[chain][pos] = w;
}

// ---------------------------------------------------------------------------
// pet2_kernel (unchanged)
// ---------------------------------------------------------------------------
__global__ void pet2_kernel(const float* __restrict__ Wc1,
                            const float* __restrict__ bc1)
{
    const int t = blockIdx.x;       // 0..255
    const int c = threadIdx.x;      // 0..287

    __shared__ float sv[2][8];
    if (c < 8) {
        double dv = exp((double)(2 * c) * (-log(10000.0) / 16.0));
        double a = (double)t * dv;
        sv[0][c] = (float)sin(a);
        sv[1][c] = (float)cos(a);
    }
    __syncthreads();

    float accS = 0.f, accR = bc1[c];
    #pragma unroll
    for (int i = 0; i < 8; i++) {
        accS = fmaf(sv[0][i], Wc1[(128 + 2 * i) * H_ + c], accS);
        accS = fmaf(sv[1][i], Wc1[(129 + 2 * i) * H_ + c], accS);
        accR = fmaf(sv[0][i], Wc1[(272 + 2 * i) * H_ + c], accR);
        accR = fmaf(sv[1][i], Wc1[(273 + 2 * i) * H_ + c], accR);
    }
    g_pet2[0][t * H_ + c] = accS;
    g_pet2[1][t * H_ + c] = accR;
}

// ---------------------------------------------------------------------------
// sort_edges (unchanged)
// ---------------------------------------------------------------------------
__global__ void sort_edges(const int* __restrict__ se, const int* __restrict__ re)
{
    __shared__ int cnt[129];
    __shared__ int cur[128];
    const int tid = threadIdx.x;    // 256 threads
    if (tid < 129) cnt[tid] = 0;
    __syncthreads();
    for (int e = tid; e < E_; e += 256) atomicAdd(&cnt[se[e] + 1], 1);
    __syncthreads();
    if (tid == 0)
        for (int i = 1; i <= 128; i++) cnt[i] += cnt[i - 1];
    __syncthreads();
    if (tid < 128) cur[tid] = cnt[tid];
    __syncthreads();
    for (int e = tid; e < E_; e += 256) {
        int s = se[e];
        int pos = atomicAdd(&cur[s], 1);
        g_se_s[pos] = s;
        g_re_s[pos] = re[e];
        g_perm[pos] = e;
    }
}

// ---------------------------------------------------------------------------
// layer128_s: full unroll, Al frags in SMEM, 2-pass fp16 (exact a@wh).
// sAl layout: sAl[kt*512 + tid*4 + q]
// ---------------------------------------------------------------------------
__device__ __forceinline__ void layer128_s(float d[16][4],
                                           u32 Ah[8][4], u32* sAl,
                                           const uint2* __restrict__ Wp,
                                           const float* __restrict__ bias,
                                           int lane, int tig, int tid)
{
    #pragma unroll
    for (int j = 0; j < 16; j++) { d[j][0]=0.f; d[j][1]=0.f; d[j][2]=0.f; d[j][3]=0.f; }
    #pragma unroll
    for (int kt = 0; kt < 8; kt++) {
        uint4 alv = *(const uint4*)(sAl + kt * 512 + tid * 4);
        u32 Al[4] = {alv.x, alv.y, alv.z, alv.w};
        #pragma unroll
        for (int j = 0; j < 16; j++) {
            uint2 w = __ldg(Wp + (kt * 16 + j) * 32 + lane);
            mma16816(d[j], Ah[kt], w.x, w.y);
            mma16816(d[j], Al,     w.x, w.y);
        }
    }
    #pragma unroll
    for (int kt = 0; kt < 8; kt++) {
        float2 bA = *(const float2*)(bias + kt * 16 + 2 * tig);
        float2 bB = *(const float2*)(bias + kt * 16 + 8 + 2 * tig);
        float p0 = fmaxf(d[2*kt][0] + bA.x, 0.f), p1 = fmaxf(d[2*kt][1] + bA.y, 0.f);
        float p2 = fmaxf(d[2*kt][2] + bA.x, 0.f), p3 = fmaxf(d[2*kt][3] + bA.y, 0.f);
        float q0 = fmaxf(d[2*kt+1][0] + bB.x, 0.f), q1 = fmaxf(d[2*kt+1][1] + bB.y, 0.f);
        float q2 = fmaxf(d[2*kt+1][2] + bB.x, 0.f), q3 = fmaxf(d[2*kt+1][3] + bB.y, 0.f);
        uint4 alv;
        Ah[kt][0] = split_packh(p0, p1, alv.x);
        Ah[kt][1] = split_packh(p2, p3, alv.y);
        Ah[kt][2] = split_packh(q0, q1, alv.z);
        Ah[kt][3] = split_packh(q2, q3, alv.w);
        *(uint4*)(sAl + kt * 512 + tid * 4) = alv;
    }
}

// ---------------------------------------------------------------------------
// chain_mma: register-resident chain, Al in smem, 3 CTAs/SM, fp16 2-pass.
// ---------------------------------------------------------------------------
__global__ __launch_bounds__(128, 3)
void chain_mma(const float* __restrict__ spikes,
               const float* __restrict__ b_emb,
               const float* __restrict__ bs1, const float* __restrict__ bs2,
               const float* __restrict__ br1, const float* __restrict__ br2)
{
    __shared__ u32 sAl[8 * 512];    // [kt][tid][q] thread-private Al frags, 16KB

    const int chain = blockIdx.y;
    const int lane  = threadIdx.x & 31;
    const int g     = lane >> 2;
    const int tig   = lane & 3;
    const int tid   = threadIdx.x;
    const int r0    = blockIdx.x * 64 + (tid >> 5) * 16 + g;

    const uint2* Wfh = g_Wfh[chain];
    const float* b1 = chain ? br1 : bs1;
    const float* b2 = chain ? br2 : bs2;
    float* Out = chain ? g_R1 : g_S1;
    const float* padd = g_pet2[chain] + ((r0 >> 7) & 255) * H_;

    u32 Ah[8][4];
    float d[16][4];

    // ---- Layer 0: emb = spikes @ W_emb + b_emb (K=16, 1 k-tile) ----------
    {
        const float* sp = spikes + (size_t)r0 * F_;
        float2 v0 = *(const float2*)(sp + 2 * tig);
        float2 v1 = *(const float2*)(sp + 8 * F_ + 2 * tig);
        float2 v2 = *(const float2*)(sp + 2 * tig + 8);
        float2 v3 = *(const float2*)(sp + 8 * F_ + 2 * tig + 8);
        u32 a0h[4], a0l[4];
        a0h[0] = split_packh(v0.x, v0.y, a0l[0]);
        a0h[1] = split_packh(v1.x, v1.y, a0l[1]);
        a0h[2] = split_packh(v2.x, v2.y, a0l[2]);
        a0h[3] = split_packh(v3.x, v3.y, a0l[3]);

        #pragma unroll
        for (int j = 0; j < 16; j++) { d[j][0]=0.f; d[j][1]=0.f; d[j][2]=0.f; d[j][3]=0.f; }
        const uint2* wp = Wfh + OFF_EMB;
        #pragma unroll
        for (int j = 0; j < 16; j++) {
            uint2 w = __ldg(wp + j * 32 + lane);
            mma16816(d[j], a0h, w.x, w.y);
            mma16816(d[j], a0l, w.x, w.y);
        }
        #pragma unroll
        for (int kt = 0; kt < 8; kt++) {
            float2 bA = *(const float2*)(b_emb + kt * 16 + 2 * tig);
            float2 bB = *(const float2*)(b_emb + kt * 16 + 8 + 2 * tig);
            float p0 = d[2*kt][0] + bA.x, p1 = d[2*kt][1] + bA.y;
            float p2 = d[2*kt][2] + bA.x, p3 = d[2*kt][3] + bA.y;
            float q0 = d[2*kt+1][0] + bB.x, q1 = d[2*kt+1][1] + bB.y;
            float q2 = d[2*kt+1][2] + bB.x, q3 = d[2*kt+1][3] + bB.y;
            uint4 alv;
            Ah[kt][0] = split_packh(p0, p1, alv.x);
            Ah[kt][1] = split_packh(p2, p3, alv.y);
            Ah[kt][2] = split_packh(q0, q1, alv.z);
            Ah[kt][3] = split_packh(q2, q3, alv.w);
            *(uint4*)(sAl + kt * 512 + tid * 4) = alv;
        }
    }

    layer128_s(d, Ah, sAl, Wfh + OFF_W1, b1, lane, tig, tid);
    layer128_s(d, Ah, sAl, Wfh + OFF_W2, b2, lane, tig, tid);

    // ---- Layer 3: Out = s @ Wc (N=288, 3 chunks of 96) ---------------------
    #pragma unroll 1
    for (int c = 0; c < 3; c++) {
        float d2[12][4];
        #pragma unroll
        for (int j = 0; j < 12; j++) { d2[j][0]=0.f; d2[j][1]=0.f; d2[j][2]=0.f; d2[j][3]=0.f; }
        const uint2* wp = Wfh + OFF_WC + c * 3072;
        #pragma unroll
        for (int kt = 0; kt < 8; kt++) {
            uint4 alv = *(const uint4*)(sAl + kt * 512 + tid * 4);
            u32 Al[4] = {alv.x, alv.y, alv.z, alv.w};
            #pragma unroll
            for (int j = 0; j < 12; j++) {
                uint2 w = __ldg(wp + (kt * 12 + j) * 32 + lane);
                mma16816(d2[j], Ah[kt], w.x, w.y);
                mma16816(d2[j], Al,     w.x, w.y);
            }
        }
        #pragma unroll
        for (int j = 0; j < 12; j++) {
            int col = c * 96 + j * 8 + 2 * tig;
            float2 pv = *(const float2*)(padd + col);
            *(float2*)(Out + (size_t)r0 * H_ + col) =
                make_float2(d2[j][0] + pv.x, d2[j][1] + pv.y);
            *(float2*)(Out + (size_t)(r0 + 8) * H_ + col) =
                make_float2(d2[j][2] + pv.x, d2[j][3] + pv.y);
        }
    }
}

// ---------------------------------------------------------------------------
// edge_kernel v3 (unchanged — sorted edges, pet folded)
// ---------------------------------------------------------------------------
__global__ __launch_bounds__(256)
void edge_kernel(const float* __restrict__ Wc2, const float* __restrict__ bc2,
                 float* __restrict__ out)
{
    __shared__ float sS[128][33];
    __shared__ float sR[128][33];
    __shared__ float sW[H_ * 5];

    const int t   = blockIdx.x;     // 0..254
    const int b   = blockIdx.y;     // 0..1
    const int tid = threadIdx.x;

    const float* Srow = g_S1 + (size_t)((b * T_ + t + 1) * N_) * H_;
    const float* Rrow = g_R1 + (size_t)((b * T_ + t) * N_) * H_;

    for (int l = tid; l < H_ * 5; l += 256) sW[l] = Wc2[l];

    float bb[5];
    #pragma unroll
    for (int j = 0; j < 5; j++) bb[j] = __ldg(bc2 + j);

    int es[4], er[4], eo[4];
    #pragma unroll
    for (int u = 0; u < 4; u++) {
        int e = u * 256 + tid;
        es[u] = g_se_s[e];
        er[u] = g_re_s[e];
        eo[u] = g_perm[e];
    }
    float acc[4][5] = {};

    #pragma unroll 1
    for (int kc = 0; kc < H_; kc += 32) {
        __syncthreads();
        #pragma unroll
        for (int it = 0; it < 4; it++) {
            int l  = tid + it * 256;
            int n  = l >> 3;
            int k4 = (l & 7) * 4;
            float4 v = *reinterpret_cast<const float4*>(Srow + (size_t)n * H_ + kc + k4);
            sS[n][k4 + 0] = v.x; sS[n][k4 + 1] = v.y;
            sS[n][k4 + 2] = v.z; sS[n][k4 + 3] = v.w;
            float4 u4 = *reinterpret_cast<const float4*>(Rrow + (size_t)n * H_ + kc + k4);
            sR[n][k4 + 0] = u4.x; sR[n][k4 + 1] = u4.y;
            sR[n][k4 + 2] = u4.z; sR[n][k4 + 3] = u4.w;
        }
        __syncthreads();
        #pragma unroll
        for (int kk = 0; kk < 32; kk++) {
            float w0 = sW[(kc + kk) * 5 + 0];
            float w1 = sW[(kc + kk) * 5 + 1];
            float w2 = sW[(kc + kk) * 5 + 2];
            float w3 = sW[(kc + kk) * 5 + 3];
            float w4 = sW[(kc + kk) * 5 + 4];
            #pragma unroll
            for (int u = 0; u < 4; u++) {
                float h = sS[es[u]][kk] + sR[er[u]][kk];
                h = fmaxf(h, 0.f);
                acc[u][0] = fmaf(h, w0, acc[u][0]);
                acc[u][1] = fmaf(h, w1, acc[u][1]);
                acc[u][2] = fmaf(h, w2, acc[u][2]);
                acc[u][3] = fmaf(h, w3, acc[u][3]);
                acc[u][4] = fmaf(h, w4, acc[u][4]);
            }
        }
    }

    #pragma unroll
    for (int u = 0; u < 4; u++) {
        size_t o = ((size_t)(b * 255 + t) * E_ + eo[u]) * 5;
        #pragma unroll
        for (int j = 0; j < 5; j++) out[o + j] = acc[u][j] + bb[j];
    }
}

// ---------------------------------------------------------------------------
extern "C" void kernel_launch(void* const* d_in, const int* in_sizes, int n_in,
                              void* d_out, int out_size)
{
    const float* spikes = (const float*)d_in[0];
    const float* W_emb  = (const float*)d_in[1];
    const float* b_emb  = (const float*)d_in[2];
    const float* Ws1    = (const float*)d_in[3];
    const float* bs1    = (const float*)d_in[4];
    const float* Ws2    = (const float*)d_in[5];
    const float* bs2    = (const float*)d_in[6];
    const float* Wr1    = (const float*)d_in[7];
    const float* br1    = (const float*)d_in[8];
    const float* Wr2    = (const float*)d_in[9];
    const float* br2    = (const float*)d_in[10];
    const float* Wc1    = (const float*)d_in[11];
    const float* bc1    = (const float*)d_in[12];
    const float* Wc2    = (const float*)d_in[13];
    const float* bc2    = (const float*)d_in[14];
    const int*   se     = (const int*)d_in[15];
    const int*   re     = (const int*)d_in[16];
    float* out = (float*)d_out;

    prep_wf<<<dim3((WF_TOTAL + 255) / 256, 2), 256>>>(
        W_emb, Ws1, Ws2, Wr1, Wr2, Wc1);

    pet2_kernel<<<256, H_>>>(Wc1, bc1);

    sort_edges<<<1, 256>>>(se, re);

    chain_mma<<<dim3(M_TOTAL / 64, 2), 128>>>(
        spikes, b_emb, bs1, bs2, br1, br2);

    edge_kernel<<<dim3(255, 2), 256>>>(Wc2, bc2, out);
}

// round 16
// speedup vs baseline: 1.5160x; 1.3160x over previous
#include <cuda_runtime.h>
#include <cuda_fp16.h>
#include <cstdint>
#include <math.h>

// Problem dims
#define B_ 2
#define T_ 256
#define N_ 128
#define F_ 16
#define D_ 128
#define H_ 288
#define E_ 1024
#define M_TOTAL (B_*T_*N_)
#define H2_ (H_/2)           // 144 half2 per row

typedef uint32_t u32;

// Scratch (allocation-free). S1/R1 now stored as half2 (u32 per 2 cols).
__device__ u32 g_S1h[(size_t)M_TOTAL * H2_];
__device__ u32 g_R1h[(size_t)M_TOTAL * H2_];
__device__ float g_pet2[2][256 * H_];     // [0]=petS(t), [1]=petR(t)+bc1
__device__ int   g_se_s[E_], g_re_s[E_], g_perm[E_];

// Fragment-ordered fp16 weight image (hi only; A carries the 2-way split).
#define OFF_EMB 0          // kt=1, NJ=16 -> 512
#define OFF_W1  512        // kt=8, NJ=16 -> 4096
#define OFF_W2  4608       // kt=8, NJ=16 -> 4096
#define OFF_WC  8704       // 3 chunks, each kt=8, NJ=12 -> 3072
#define WF_TOTAL 17920
__device__ uint2 g_Wfh[2][WF_TOTAL];

// ---------------- helpers ---------------------------------------------------
__device__ __forceinline__ u32 pack2h(__half a, __half b) {
    return ((u32)__half_as_ushort(b) << 16) | (u32)__half_as_ushort(a);
}
__device__ __forceinline__ u32 split_packh(float v0, float v1, u32& lo) {
    __half h0 = __float2half_rn(v0);
    __half h1 = __float2half_rn(v1);
    lo = pack2h(__float2half_rn(v0 - __half2float(h0)),
                __float2half_rn(v1 - __half2float(h1)));
    return pack2h(h0, h1);
}
__device__ __forceinline__ void mma16816(float* d, const u32* a, u32 b0, u32 b1) {
    asm volatile(
        "mma.sync.aligned.m16n8k16.row.col.f32.f16.f16.f32 "
        "{%0,%1,%2,%3}, {%4,%5,%6,%7}, {%8,%9}, {%0,%1,%2,%3};"
        : "+f"(d[0]), "+f"(d[1]), "+f"(d[2]), "+f"(d[3])
        : "r"(a[0]), "r"(a[1]), "r"(a[2]), "r"(a[3]), "r"(b0), "r"(b1));
}

// ---------------------------------------------------------------------------
// prep_wf (unchanged from R15)
// ---------------------------------------------------------------------------
__global__ void prep_wf(const float* __restrict__ W_emb,
                        const float* __restrict__ Ws1, const float* __restrict__ Ws2,
                        const float* __restrict__ Wr1, const float* __restrict__ Wr2,
                        const float* __restrict__ Wc1)
{
    const int chain = blockIdx.y;
    int pos = blockIdx.x * 256 + threadIdx.x;
    if (pos >= WF_TOTAL) return;

    const float* W; int rel, NJ, N = 128, koff = 0, coff = 0;
    if (pos < OFF_W1)      { rel = pos;          NJ = 16; W = W_emb; }
    else if (pos < OFF_W2) { rel = pos - OFF_W1; NJ = 16; W = chain ? Wr1 : Ws1; }
    else if (pos < OFF_WC) { rel = pos - OFF_W2; NJ = 16; W = chain ? Wr2 : Ws2; }
    else {
        int rel2 = pos - OFF_WC;
        int c = rel2 / 3072; rel = rel2 % 3072;
        NJ = 12; W = Wc1; N = 288; koff = chain ? 144 : 0; coff = 96 * c;
    }
    int lane = rel & 31;
    int t    = rel >> 5;
    int j    = t % NJ;
    int kt   = t / NJ;
    int gg   = lane >> 2;
    int tg   = lane & 3;
    int n    = coff + 8 * j + gg;

    uint2 w;
    {
        int k = kt * 16 + 2 * tg;
        w.x = pack2h(__float2half_rn(W[(size_t)(k + koff) * N + n]),
                     __float2half_rn(W[(size_t)(k + 1 + koff) * N + n]));
    }
    {
        int k = kt * 16 + 8 + 2 * tg;
        w.y = pack2h(__float2half_rn(W[(size_t)(k + koff) * N + n]),
                     __float2half_rn(W[(size_t)(k + 1 + koff) * N + n]));
    }
    g_Wfh[chain][pos] = w;
}

// ---------------------------------------------------------------------------
// pet2_kernel (unchanged)
// ---------------------------------------------------------------------------
__global__ void pet2_kernel(const float* __restrict__ Wc1,
                            const float* __restrict__ bc1)
{
    const int t = blockIdx.x;
    const int c = threadIdx.x;

    __shared__ float sv[2][8];
    if (c < 8) {
        double dv = exp((double)(2 * c) * (-log(10000.0) / 16.0));
        double a = (double)t * dv;
        sv[0][c] = (float)sin(a);
        sv[1][c] = (float)cos(a);
    }
    __syncthreads();

    float accS = 0.f, accR = bc1[c];
    #pragma unroll
    for (int i = 0; i < 8; i++) {
        accS = fmaf(sv[0][i], Wc1[(128 + 2 * i) * H_ + c], accS);
        accS = fmaf(sv[1][i], Wc1[(129 + 2 * i) * H_ + c], accS);
        accR = fmaf(sv[0][i], Wc1[(272 + 2 * i) * H_ + c], accR);
        accR = fmaf(sv[1][i], Wc1[(273 + 2 * i) * H_ + c], accR);
    }
    g_pet2[0][t * H_ + c] = accS;
    g_pet2[1][t * H_ + c] = accR;
}

// ---------------------------------------------------------------------------
// sort_edges (unchanged)
// ---------------------------------------------------------------------------
__global__ void sort_edges(const int* __restrict__ se, const int* __restrict__ re)
{
    __shared__ int cnt[129];
    __shared__ int cur[128];
    const int tid = threadIdx.x;
    if (tid < 129) cnt[tid] = 0;
    __syncthreads();
    for (int e = tid; e < E_; e += 256) atomicAdd(&cnt[se[e] + 1], 1);
    __syncthreads();
    if (tid == 0)
        for (int i = 1; i <= 128; i++) cnt[i] += cnt[i - 1];
    __syncthreads();
    if (tid < 128) cur[tid] = cnt[tid];
    __syncthreads();
    for (int e = tid; e < E_; e += 256) {
        int s = se[e];
        int pos = atomicAdd(&cur[s], 1);
        g_se_s[pos] = s;
        g_re_s[pos] = re[e];
        g_perm[pos] = e;
    }
}

// ---------------------------------------------------------------------------
// layer128_s: full unroll, BOTH Ah and Al frags in SMEM (thread-private uint4
// slots) -> arch regs ~= d only -> 4 CTAs/SM.
// layout: sA[kt*512 + tid*4 + q]
// ---------------------------------------------------------------------------
__device__ __forceinline__ void layer128_s(float d[16][4],
                                           u32* sAh, u32* sAl,
                                           const uint2* __restrict__ Wp,
                                           const float* __restrict__ bias,
                                           int lane, int tig, int tid)
{
    #pragma unroll
    for (int j = 0; j < 16; j++) { d[j][0]=0.f; d[j][1]=0.f; d[j][2]=0.f; d[j][3]=0.f; }
    #pragma unroll
    for (int kt = 0; kt < 8; kt++) {
        uint4 ahv = *(const uint4*)(sAh + kt * 512 + tid * 4);
        uint4 alv = *(const uint4*)(sAl + kt * 512 + tid * 4);
        u32 Ah[4] = {ahv.x, ahv.y, ahv.z, ahv.w};
        u32 Al[4] = {alv.x, alv.y, alv.z, alv.w};
        #pragma unroll
        for (int j = 0; j < 16; j++) {
            uint2 w = __ldg(Wp + (kt * 16 + j) * 32 + lane);
            mma16816(d[j], Ah, w.x, w.y);
            mma16816(d[j], Al, w.x, w.y);
        }
    }
    #pragma unroll
    for (int kt = 0; kt < 8; kt++) {
        float2 bA = *(const float2*)(bias + kt * 16 + 2 * tig);
        float2 bB = *(const float2*)(bias + kt * 16 + 8 + 2 * tig);
        float p0 = fmaxf(d[2*kt][0] + bA.x, 0.f), p1 = fmaxf(d[2*kt][1] + bA.y, 0.f);
        float p2 = fmaxf(d[2*kt][2] + bA.x, 0.f), p3 = fmaxf(d[2*kt][3] + bA.y, 0.f);
        float q0 = fmaxf(d[2*kt+1][0] + bB.x, 0.f), q1 = fmaxf(d[2*kt+1][1] + bB.y, 0.f);
        float q2 = fmaxf(d[2*kt+1][2] + bB.x, 0.f), q3 = fmaxf(d[2*kt+1][3] + bB.y, 0.f);
        uint4 ahv, alv;
        ahv.x = split_packh(p0, p1, alv.x);
        ahv.y = split_packh(p2, p3, alv.y);
        ahv.z = split_packh(q0, q1, alv.z);
        ahv.w = split_packh(q2, q3, alv.w);
        *(uint4*)(sAh + kt * 512 + tid * 4) = ahv;
        *(uint4*)(sAl + kt * 512 + tid * 4) = alv;
    }
}

// ---------------------------------------------------------------------------
// chain_mma: A frags (hi+lo) in smem, d in regs, 4 CTAs/SM, fp16 2-pass.
// Output stored as half2 (u32) for the edge kernel.
// ---------------------------------------------------------------------------
__global__ __launch_bounds__(128, 4)
void chain_mma(const float* __restrict__ spikes,
               const float* __restrict__ b_emb,
               const float* __restrict__ bs1, const float* __restrict__ bs2,
               const float* __restrict__ br1, const float* __restrict__ br2)
{
    __shared__ u32 sAh[8 * 512];    // 16KB
    __shared__ u32 sAl[8 * 512];    // 16KB

    const int chain = blockIdx.y;
    const int lane  = threadIdx.x & 31;
    const int g     = lane >> 2;
    const int tig   = lane & 3;
    const int tid   = threadIdx.x;
    const int r0    = blockIdx.x * 64 + (tid >> 5) * 16 + g;

    const uint2* Wfh = g_Wfh[chain];
    const float* b1 = chain ? br1 : bs1;
    const float* b2 = chain ? br2 : bs2;
    u32* Out = chain ? g_R1h : g_S1h;
    const float* padd = g_pet2[chain] + ((r0 >> 7) & 255) * H_;

    float d[16][4];

    // ---- Layer 0: emb = spikes @ W_emb + b_emb (K=16, 1 k-tile) ----------
    {
        const float* sp = spikes + (size_t)r0 * F_;
        float2 v0 = *(const float2*)(sp + 2 * tig);
        float2 v1 = *(const float2*)(sp + 8 * F_ + 2 * tig);
        float2 v2 = *(const float2*)(sp + 2 * tig + 8);
        float2 v3 = *(const float2*)(sp + 8 * F_ + 2 * tig + 8);
        u32 a0h[4], a0l[4];
        a0h[0] = split_packh(v0.x, v0.y, a0l[0]);
        a0h[1] = split_packh(v1.x, v1.y, a0l[1]);
        a0h[2] = split_packh(v2.x, v2.y, a0l[2]);
        a0h[3] = split_packh(v3.x, v3.y, a0l[3]);

        #pragma unroll
        for (int j = 0; j < 16; j++) { d[j][0]=0.f; d[j][1]=0.f; d[j][2]=0.f; d[j][3]=0.f; }
        const uint2* wp = Wfh + OFF_EMB;
        #pragma unroll
        for (int j = 0; j < 16; j++) {
            uint2 w = __ldg(wp + j * 32 + lane);
            mma16816(d[j], a0h, w.x, w.y);
            mma16816(d[j], a0l, w.x, w.y);
        }
        #pragma unroll
        for (int kt = 0; kt < 8; kt++) {
            float2 bA = *(const float2*)(b_emb + kt * 16 + 2 * tig);
            float2 bB = *(const float2*)(b_emb + kt * 16 + 8 + 2 * tig);
            float p0 = d[2*kt][0] + bA.x, p1 = d[2*kt][1] + bA.y;
            float p2 = d[2*kt][2] + bA.x, p3 = d[2*kt][3] + bA.y;
            float q0 = d[2*kt+1][0] + bB.x, q1 = d[2*kt+1][1] + bB.y;
            float q2 = d[2*kt+1][2] + bB.x, q3 = d[2*kt+1][3] + bB.y;
            uint4 ahv, alv;
            ahv.x = split_packh(p0, p1, alv.x);
            ahv.y = split_packh(p2, p3, alv.y);
            ahv.z = split_packh(q0, q1, alv.z);
            ahv.w = split_packh(q2, q3, alv.w);
            *(uint4*)(sAh + kt * 512 + tid * 4) = ahv;
            *(uint4*)(sAl + kt * 512 + tid * 4) = alv;
        }
    }

    layer128_s(d, sAh, sAl, Wfh + OFF_W1, b1, lane, tig, tid);
    layer128_s(d, sAh, sAl, Wfh + OFF_W2, b2, lane, tig, tid);

    // ---- Layer 3: Out = s @ Wc (N=288, 3 chunks of 96), half2 stores ------
    #pragma unroll 1
    for (int c = 0; c < 3; c++) {
        float d2[12][4];
        #pragma unroll
        for (int j = 0; j < 12; j++) { d2[j][0]=0.f; d2[j][1]=0.f; d2[j][2]=0.f; d2[j][3]=0.f; }
        const uint2* wp = Wfh + OFF_WC + c * 3072;
        #pragma unroll
        for (int kt = 0; kt < 8; kt++) {
            uint4 ahv = *(const uint4*)(sAh + kt * 512 + tid * 4);
            uint4 alv = *(const uint4*)(sAl + kt * 512 + tid * 4);
            u32 Ah[4] = {ahv.x, ahv.y, ahv.z, ahv.w};
            u32 Al[4] = {alv.x, alv.y, alv.z, alv.w};
            #pragma unroll
            for (int j = 0; j < 12; j++) {
                uint2 w = __ldg(wp + (kt * 12 + j) * 32 + lane);
                mma16816(d2[j], Ah, w.x, w.y);
                mma16816(d2[j], Al, w.x, w.y);
            }
        }
        #pragma unroll
        for (int j = 0; j < 12; j++) {
            int col  = c * 96 + j * 8 + 2 * tig;
            int col2 = col >> 1;
            float2 pv = *(const float2*)(padd + col);
            __half2 lo = __floats2half2_rn(d2[j][0] + pv.x, d2[j][1] + pv.y);
            __half2 hi = __floats2half2_rn(d2[j][2] + pv.x, d2[j][3] + pv.y);
            Out[(size_t)r0 * H2_ + col2]       = *(u32*)&lo;
            Out[(size_t)(r0 + 8) * H2_ + col2] = *(u32*)&hi;
        }
    }
}

// ---------------------------------------------------------------------------
// edge_kernel v4: half2 gathers (1 LDS covers 2 k), sorted edges, pet folded.
// sS/sR layout: [row][17 u32] (16 half2 per 32-k chunk + pad)
// ---------------------------------------------------------------------------
__global__ __launch_bounds__(256)
void edge_kernel(const float* __restrict__ Wc2, const float* __restrict__ bc2,
                 float* __restrict__ out)
{
    __shared__ u32 sS[128 * 17];
    __shared__ u32 sR[128 * 17];
    __shared__ float sW[H_ * 5];

    const int t   = blockIdx.x;     // 0..254
    const int b   = blockIdx.y;     // 0..1
    const int tid = threadIdx.x;

    const u32* Srow = g_S1h + (size_t)((b * T_ + t + 1) * N_) * H2_;
    const u32* Rrow = g_R1h + (size_t)((b * T_ + t) * N_) * H2_;

    for (int l = tid; l < H_ * 5; l += 256) sW[l] = Wc2[l];

    float bb[5];
    #pragma unroll
    for (int j = 0; j < 5; j++) bb[j] = __ldg(bc2 + j);

    int es[4], er[4], eo[4];
    #pragma unroll
    for (int u = 0; u < 4; u++) {
        int e = u * 256 + tid;      // sorted index; lanes adjacent -> se coherent
        es[u] = g_se_s[e] * 17;
        er[u] = g_re_s[e] * 17;
        eo[u] = g_perm[e];
    }
    float acc[4][5] = {};
    const __half2 zero2 = __floats2half2_rn(0.f, 0.f);

    #pragma unroll 1
    for (int kc = 0; kc < H_; kc += 32) {
        const int kc2 = kc >> 1;    // u32 offset in row
        __syncthreads();
        #pragma unroll
        for (int it = 0; it < 2; it++) {
            int l = tid + it * 256;      // 0..511
            int n = l >> 2;
            int q = l & 3;
            uint4 v = *(const uint4*)(Srow + (size_t)n * H2_ + kc2 + q * 4);
            u32* ds = sS + n * 17 + q * 4;
            ds[0] = v.x; ds[1] = v.y; ds[2] = v.z; ds[3] = v.w;
            uint4 w = *(const uint4*)(Rrow + (size_t)n * H2_ + kc2 + q * 4);
            u32* dr = sR + n * 17 + q * 4;
            dr[0] = w.x; dr[1] = w.y; dr[2] = w.z; dr[3] = w.w;
        }
        __syncthreads();
        #pragma unroll
        for (int kk2 = 0; kk2 < 16; kk2++) {
            const int k0 = kc + 2 * kk2;
            float wA[5], wB[5];
            #pragma unroll
            for (int j = 0; j < 5; j++) {
                wA[j] = sW[k0 * 5 + j];
                wB[j] = sW[(k0 + 1) * 5 + j];
            }
            #pragma unroll
            for (int u = 0; u < 4; u++) {
                u32 sv = sS[es[u] + kk2];
                u32 rv = sR[er[u] + kk2];
                __half2 s2 = *reinterpret_cast<const __half2*>(&sv);
                __half2 r2 = *reinterpret_cast<const __half2*>(&rv);
                __half2 h2 = __hmax2(__hadd2(s2, r2), zero2);
                float2 f = __half22float2(h2);
                #pragma unroll
                for (int j = 0; j < 5; j++)
                    acc[u][j] = fmaf(f.x, wA[j], fmaf(f.y, wB[j], acc[u][j]));
            }
        }
    }

    #pragma unroll
    for (int u = 0; u < 4; u++) {
        size_t o = ((size_t)(b * 255 + t) * E_ + eo[u]) * 5;
        #pragma unroll
        for (int j = 0; j < 5; j++) out[o + j] = acc[u][j] + bb[j];
    }
}

// ---------------------------------------------------------------------------
extern "C" void kernel_launch(void* const* d_in, const int* in_sizes, int n_in,
                              void* d_out, int out_size)
{
    const float* spikes = (const float*)d_in[0];
    const float* W_emb  = (const float*)d_in[1];
    const float* b_emb  = (const float*)d_in[2];
    const float* Ws1    = (const float*)d_in[3];
    const float* bs1    = (const float*)d_in[4];
    const float* Ws2    = (const float*)d_in[5];
    const float* bs2    = (const float*)d_in[6];
    const float* Wr1    = (const float*)d_in[7];
    const float* br1    = (const float*)d_in[8];
    const float* Wr2    = (const float*)d_in[9];
    const float* br2    = (const float*)d_in[10];
    const float* Wc1    = (const float*)d_in[11];
    const float* bc1    = (const float*)d_in[12];
    const float* Wc2    = (const float*)d_in[13];
    const float* bc2    = (const float*)d_in[14];
    const int*   se     = (const int*)d_in[15];
    const int*   re     = (const int*)d_in[16];
    float* out = (float*)d_out;

    prep_wf<<<dim3((WF_TOTAL + 255) / 256, 2), 256>>>(
        W_emb, Ws1, Ws2, Wr1, Wr2, Wc1);

    pet2_kernel<<<256, H_>>>(Wc1, bc1);

    sort_edges<<<1, 256>>>(se, re);

    chain_mma<<<dim3(M_TOTAL / 64, 2), 128>>>(
        spikes, b_emb, bs1, bs2, br1, br2);

    edge_kernel<<<dim3(255, 2), 256>>>(Wc2, bc2, out);
}

// round 17
// speedup vs baseline: 1.5647x; 1.0321x over previous
#include <cuda_runtime.h>
#include <cuda_fp16.h>
#include <cstdint>
#include <math.h>

// Problem dims
#define B_ 2
#define T_ 256
#define N_ 128
#define F_ 16
#define D_ 128
#define H_ 288
#define E_ 1024
#define M_TOTAL (B_*T_*N_)
#define H2_ (H_/2)           // 144 half2 per row

typedef uint32_t u32;

// Scratch (allocation-free). S1/R1 stored as half2 (u32 per 2 cols).
__device__ u32 g_S1h[(size_t)M_TOTAL * H2_];
__device__ u32 g_R1h[(size_t)M_TOTAL * H2_];
__device__ float g_pet2[2][256 * H_];     // [0]=petS(t), [1]=petR(t)+bc1
__device__ int   g_se_s[E_], g_re_s[E_], g_perm[E_];

// Fragment-ordered fp16 weight image (hi only; A carries the 2-way split).
#define OFF_EMB 0          // kt=1, NJ=16 -> 512
#define OFF_W1  512        // kt=8, NJ=16 -> 4096
#define OFF_W2  4608       // kt=8, NJ=16 -> 4096
#define OFF_WC  8704       // 3 chunks, each kt=8, NJ=12 -> 3072
#define WF_TOTAL 17920
__device__ uint2 g_Wfh[2][WF_TOTAL];

// ---------------- helpers ---------------------------------------------------
__device__ __forceinline__ u32 pack2h(__half a, __half b) {
    return ((u32)__half_as_ushort(b) << 16) | (u32)__half_as_ushort(a);
}
__device__ __forceinline__ u32 split_packh(float v0, float v1, u32& lo) {
    __half h0 = __float2half_rn(v0);
    __half h1 = __float2half_rn(v1);
    lo = pack2h(__float2half_rn(v0 - __half2float(h0)),
                __float2half_rn(v1 - __half2float(h1)));
    return pack2h(h0, h1);
}
__device__ __forceinline__ void mma16816(float* d, const u32* a, u32 b0, u32 b1) {
    asm volatile(
        "mma.sync.aligned.m16n8k16.row.col.f32.f16.f16.f32 "
        "{%0,%1,%2,%3}, {%4,%5,%6,%7}, {%8,%9}, {%0,%1,%2,%3};"
        : "+f"(d[0]), "+f"(d[1]), "+f"(d[2]), "+f"(d[3])
        : "r"(a[0]), "r"(a[1]), "r"(a[2]), "r"(a[3]), "r"(b0), "r"(b1));
}

// ---------------------------------------------------------------------------
// aux_prep: ONE kernel doing prep_wf (blocks 0..139), pet2 (140..395),
// sort_edges (396). All three parts are mutually independent.
// ---------------------------------------------------------------------------
__global__ void aux_prep(const float* __restrict__ W_emb,
                         const float* __restrict__ Ws1, const float* __restrict__ Ws2,
                         const float* __restrict__ Wr1, const float* __restrict__ Wr2,
                         const float* __restrict__ Wc1, const float* __restrict__ bc1,
                         const int* __restrict__ se, const int* __restrict__ re)
{
    const int blk = blockIdx.x;
    const int tid = threadIdx.x;

    if (blk < 140) {
        // ---- prep_wf ----
        const int chain = blk / 70;
        int pos = (blk % 70) * 256 + tid;
        if (pos >= WF_TOTAL) return;

        const float* W; int rel, NJ, N = 128, koff = 0, coff = 0;
        if (pos < OFF_W1)      { rel = pos;          NJ = 16; W = W_emb; }
        else if (pos < OFF_W2) { rel = pos - OFF_W1; NJ = 16; W = chain ? Wr1 : Ws1; }
        else if (pos < OFF_WC) { rel = pos - OFF_W2; NJ = 16; W = chain ? Wr2 : Ws2; }
        else {
            int rel2 = pos - OFF_WC;
            int c = rel2 / 3072; rel = rel2 % 3072;
            NJ = 12; W = Wc1; N = 288; koff = chain ? 144 : 0; coff = 96 * c;
        }
        int lane = rel & 31;
        int t    = rel >> 5;
        int j    = t % NJ;
        int kt   = t / NJ;
        int gg   = lane >> 2;
        int tg   = lane & 3;
        int n    = coff + 8 * j + gg;

        uint2 w;
        {
            int k = kt * 16 + 2 * tg;
            w.x = pack2h(__float2half_rn(W[(size_t)(k + koff) * N + n]),
                         __float2half_rn(W[(size_t)(k + 1 + koff) * N + n]));
        }
        {
            int k = kt * 16 + 8 + 2 * tg;
            w.y = pack2h(__float2half_rn(W[(size_t)(k + koff) * N + n]),
                         __float2half_rn(W[(size_t)(k + 1 + koff) * N + n]));
        }
        g_Wfh[chain][pos] = w;
    } else if (blk < 396) {
        // ---- pet2 (t = blk - 140), 256 threads loop over 288 cols ----
        const int t = blk - 140;
        __shared__ float sv[2][8];
        if (tid < 8) {
            double dv = exp((double)(2 * tid) * (-log(10000.0) / 16.0));
            double a = (double)t * dv;
            sv[0][tid] = (float)sin(a);
            sv[1][tid] = (float)cos(a);
        }
        __syncthreads();
        for (int c = tid; c < H_; c += 256) {
            float accS = 0.f, accR = bc1[c];
            #pragma unroll
            for (int i = 0; i < 8; i++) {
                accS = fmaf(sv[0][i], Wc1[(128 + 2 * i) * H_ + c], accS);
                accS = fmaf(sv[1][i], Wc1[(129 + 2 * i) * H_ + c], accS);
                accR = fmaf(sv[0][i], Wc1[(272 + 2 * i) * H_ + c], accR);
                accR = fmaf(sv[1][i], Wc1[(273 + 2 * i) * H_ + c], accR);
            }
            g_pet2[0][t * H_ + c] = accS;
            g_pet2[1][t * H_ + c] = accR;
        }
    } else {
        // ---- sort_edges (counting sort by se) ----
        __shared__ int cnt[129];
        __shared__ int cur[128];
        if (tid < 129) cnt[tid] = 0;
        __syncthreads();
        for (int e = tid; e < E_; e += 256) atomicAdd(&cnt[se[e] + 1], 1);
        __syncthreads();
        if (tid == 0)
            for (int i = 1; i <= 128; i++) cnt[i] += cnt[i - 1];
        __syncthreads();
        if (tid < 128) cur[tid] = cnt[tid];
        __syncthreads();
        for (int e = tid; e < E_; e += 256) {
            int s = se[e];
            int pos = atomicAdd(&cur[s], 1);
            g_se_s[pos] = s;
            g_re_s[pos] = re[e];
            g_perm[pos] = e;
        }
    }
}

// ---------------------------------------------------------------------------
// layer128_s: full unroll, BOTH Ah and Al frags in SMEM (thread-private uint4
// slots) -> 4 CTAs/SM. layout: sA[kt*512 + tid*4 + q]
// ---------------------------------------------------------------------------
__device__ __forceinline__ void layer128_s(float d[16][4],
                                           u32* sAh, u32* sAl,
                                           const uint2* __restrict__ Wp,
                                           const float* __restrict__ bias,
                                           int lane, int tig, int tid)
{
    #pragma unroll
    for (int j = 0; j < 16; j++) { d[j][0]=0.f; d[j][1]=0.f; d[j][2]=0.f; d[j][3]=0.f; }
    #pragma unroll
    for (int kt = 0; kt < 8; kt++) {
        uint4 ahv = *(const uint4*)(sAh + kt * 512 + tid * 4);
        uint4 alv = *(const uint4*)(sAl + kt * 512 + tid * 4);
        u32 Ah[4] = {ahv.x, ahv.y, ahv.z, ahv.w};
        u32 Al[4] = {alv.x, alv.y, alv.z, alv.w};
        #pragma unroll
        for (int j = 0; j < 16; j++) {
            uint2 w = __ldg(Wp + (kt * 16 + j) * 32 + lane);
            mma16816(d[j], Ah, w.x, w.y);
            mma16816(d[j], Al, w.x, w.y);
        }
    }
    #pragma unroll
    for (int kt = 0; kt < 8; kt++) {
        float2 bA = *(const float2*)(bias + kt * 16 + 2 * tig);
        float2 bB = *(const float2*)(bias + kt * 16 + 8 + 2 * tig);
        float p0 = fmaxf(d[2*kt][0] + bA.x, 0.f), p1 = fmaxf(d[2*kt][1] + bA.y, 0.f);
        float p2 = fmaxf(d[2*kt][2] + bA.x, 0.f), p3 = fmaxf(d[2*kt][3] + bA.y, 0.f);
        float q0 = fmaxf(d[2*kt+1][0] + bB.x, 0.f), q1 = fmaxf(d[2*kt+1][1] + bB.y, 0.f);
        float q2 = fmaxf(d[2*kt+1][2] + bB.x, 0.f), q3 = fmaxf(d[2*kt+1][3] + bB.y, 0.f);
        uint4 ahv, alv;
        ahv.x = split_packh(p0, p1, alv.x);
        ahv.y = split_packh(p2, p3, alv.y);
        ahv.z = split_packh(q0, q1, alv.z);
        ahv.w = split_packh(q2, q3, alv.w);
        *(uint4*)(sAh + kt * 512 + tid * 4) = ahv;
        *(uint4*)(sAl + kt * 512 + tid * 4) = alv;
    }
}

// ---------------------------------------------------------------------------
// chain_mma: A frags (hi+lo) in smem, d in regs, 4 CTAs/SM, fp16 2-pass.
// Output stored as half2 for the edge kernel. (unchanged from R16)
// ---------------------------------------------------------------------------
__global__ __launch_bounds__(128, 4)
void chain_mma(const float* __restrict__ spikes,
               const float* __restrict__ b_emb,
               const float* __restrict__ bs1, const float* __restrict__ bs2,
               const float* __restrict__ br1, const float* __restrict__ br2)
{
    __shared__ u32 sAh[8 * 512];    // 16KB
    __shared__ u32 sAl[8 * 512];    // 16KB

    const int chain = blockIdx.y;
    const int lane  = threadIdx.x & 31;
    const int g     = lane >> 2;
    const int tig   = lane & 3;
    const int tid   = threadIdx.x;
    const int r0    = blockIdx.x * 64 + (tid >> 5) * 16 + g;

    const uint2* Wfh = g_Wfh[chain];
    const float* b1 = chain ? br1 : bs1;
    const float* b2 = chain ? br2 : bs2;
    u32* Out = chain ? g_R1h : g_S1h;
    const float* padd = g_pet2[chain] + ((r0 >> 7) & 255) * H_;

    float d[16][4];

    // ---- Layer 0: emb = spikes @ W_emb + b_emb (K=16, 1 k-tile) ----------
    {
        const float* sp = spikes + (size_t)r0 * F_;
        float2 v0 = *(const float2*)(sp + 2 * tig);
        float2 v1 = *(const float2*)(sp + 8 * F_ + 2 * tig);
        float2 v2 = *(const float2*)(sp + 2 * tig + 8);
        float2 v3 = *(const float2*)(sp + 8 * F_ + 2 * tig + 8);
        u32 a0h[4], a0l[4];
        a0h[0] = split_packh(v0.x, v0.y, a0l[0]);
        a0h[1] = split_packh(v1.x, v1.y, a0l[1]);
        a0h[2] = split_packh(v2.x, v2.y, a0l[2]);
        a0h[3] = split_packh(v3.x, v3.y, a0l[3]);

        #pragma unroll
        for (int j = 0; j < 16; j++) { d[j][0]=0.f; d[j][1]=0.f; d[j][2]=0.f; d[j][3]=0.f; }
        const uint2* wp = Wfh + OFF_EMB;
        #pragma unroll
        for (int j = 0; j < 16; j++) {
            uint2 w = __ldg(wp + j * 32 + lane);
            mma16816(d[j], a0h, w.x, w.y);
            mma16816(d[j], a0l, w.x, w.y);
        }
        #pragma unroll
        for (int kt = 0; kt < 8; kt++) {
            float2 bA = *(const float2*)(b_emb + kt * 16 + 2 * tig);
            float2 bB = *(const float2*)(b_emb + kt * 16 + 8 + 2 * tig);
            float p0 = d[2*kt][0] + bA.x, p1 = d[2*kt][1] + bA.y;
            float p2 = d[2*kt][2] + bA.x, p3 = d[2*kt][3] + bA.y;
            float q0 = d[2*kt+1][0] + bB.x, q1 = d[2*kt+1][1] + bB.y;
            float q2 = d[2*kt+1][2] + bB.x, q3 = d[2*kt+1][3] + bB.y;
            uint4 ahv, alv;
            ahv.x = split_packh(p0, p1, alv.x);
            ahv.y = split_packh(p2, p3, alv.y);
            ahv.z = split_packh(q0, q1, alv.z);
            ahv.w = split_packh(q2, q3, alv.w);
            *(uint4*)(sAh + kt * 512 + tid * 4) = ahv;
            *(uint4*)(sAl + kt * 512 + tid * 4) = alv;
        }
    }

    layer128_s(d, sAh, sAl, Wfh + OFF_W1, b1, lane, tig, tid);
    layer128_s(d, sAh, sAl, Wfh + OFF_W2, b2, lane, tig, tid);

    // ---- Layer 3: Out = s @ Wc (N=288, 3 chunks of 96), half2 stores ------
    #pragma unroll 1
    for (int c = 0; c < 3; c++) {
        float d2[12][4];
        #pragma unroll
        for (int j = 0; j < 12; j++) { d2[j][0]=0.f; d2[j][1]=0.f; d2[j][2]=0.f; d2[j][3]=0.f; }
        const uint2* wp = Wfh + OFF_WC + c * 3072;
        #pragma unroll
        for (int kt = 0; kt < 8; kt++) {
            uint4 ahv = *(const uint4*)(sAh + kt * 512 + tid * 4);
            uint4 alv = *(const uint4*)(sAl + kt * 512 + tid * 4);
            u32 Ah[4] = {ahv.x, ahv.y, ahv.z, ahv.w};
            u32 Al[4] = {alv.x, alv.y, alv.z, alv.w};
            #pragma unroll
            for (int j = 0; j < 12; j++) {
                uint2 w = __ldg(wp + (kt * 12 + j) * 32 + lane);
                mma16816(d2[j], Ah, w.x, w.y);
                mma16816(d2[j], Al, w.x, w.y);
            }
        }
        #pragma unroll
        for (int j = 0; j < 12; j++) {
            int col  = c * 96 + j * 8 + 2 * tig;
            int col2 = col >> 1;
            float2 pv = *(const float2*)(padd + col);
            __half2 lo = __floats2half2_rn(d2[j][0] + pv.x, d2[j][1] + pv.y);
            __half2 hi = __floats2half2_rn(d2[j][2] + pv.x, d2[j][3] + pv.y);
            Out[(size_t)r0 * H2_ + col2]       = *(u32*)&lo;
            Out[(size_t)(r0 + 8) * H2_ + col2] = *(u32*)&hi;
        }
    }
}

// ---------------------------------------------------------------------------
// edge_kernel v5: half2 gathers + register-staged prefetch of the next
// 32-k chunk (overlaps DRAM latency with compute).
// sS/sR layout: [row][17 u32]
// ---------------------------------------------------------------------------
__global__ __launch_bounds__(256)
void edge_kernel(const float* __restrict__ Wc2, const float* __restrict__ bc2,
                 float* __restrict__ out)
{
    __shared__ u32 sS[128 * 17];
    __shared__ u32 sR[128 * 17];
    __shared__ float sW[H_ * 5];

    const int t   = blockIdx.x;     // 0..254
    const int b   = blockIdx.y;     // 0..1
    const int tid = threadIdx.x;

    const u32* Srow = g_S1h + (size_t)((b * T_ + t + 1) * N_) * H2_;
    const u32* Rrow = g_R1h + (size_t)((b * T_ + t) * N_) * H2_;

    for (int l = tid; l < H_ * 5; l += 256) sW[l] = Wc2[l];

    float bb[5];
    #pragma unroll
    for (int j = 0; j < 5; j++) bb[j] = __ldg(bc2 + j);

    int es[4], er[4], eo[4];
    #pragma unroll
    for (int u = 0; u < 4; u++) {
        int e = u * 256 + tid;      // sorted index; lanes adjacent -> se coherent
        es[u] = g_se_s[e] * 17;
        er[u] = g_re_s[e] * 17;
        eo[u] = g_perm[e];
    }
    float acc[4][5] = {};
    const __half2 zero2 = __floats2half2_rn(0.f, 0.f);

    // per-thread staging slots: l = tid + it*256; n = l>>2, q = l&3
    const int n0 = tid >> 2,        q0 = tid & 3;
    const int n1 = (tid + 256) >> 2, q1 = (tid + 256) & 3;

    uint4 pS[2], pR[2];
    pS[0] = *(const uint4*)(Srow + (size_t)n0 * H2_ + q0 * 4);
    pR[0] = *(const uint4*)(Rrow + (size_t)n0 * H2_ + q0 * 4);
    pS[1] = *(const uint4*)(Srow + (size_t)n1 * H2_ + q1 * 4);
    pR[1] = *(const uint4*)(Rrow + (size_t)n1 * H2_ + q1 * 4);

    #pragma unroll 1
    for (int kc = 0; kc < H_; kc += 32) {
        __syncthreads();      // prior compute done; smem free to overwrite
        {
            u32* ds0 = sS + n0 * 17 + q0 * 4;
            ds0[0] = pS[0].x; ds0[1] = pS[0].y; ds0[2] = pS[0].z; ds0[3] = pS[0].w;
            u32* dr0 = sR + n0 * 17 + q0 * 4;
            dr0[0] = pR[0].x; dr0[1] = pR[0].y; dr0[2] = pR[0].z; dr0[3] = pR[0].w;
            u32* ds1 = sS + n1 * 17 + q1 * 4;
            ds1[0] = pS[1].x; ds1[1] = pS[1].y; ds1[2] = pS[1].z; ds1[3] = pS[1].w;
            u32* dr1 = sR + n1 * 17 + q1 * 4;
            dr1[0] = pR[1].x; dr1[1] = pR[1].y; dr1[2] = pR[1].z; dr1[3] = pR[1].w;
        }
        __syncthreads();      // smem chunk ready
        if (kc + 32 < H_) {   // prefetch next chunk (LDGs overlap compute)
            const int kc2n = (kc + 32) >> 1;
            pS[0] = *(const uint4*)(Srow + (size_t)n0 * H2_ + kc2n + q0 * 4);
            pR[0] = *(const uint4*)(Rrow + (size_t)n0 * H2_ + kc2n + q0 * 4);
            pS[1] = *(const uint4*)(Srow + (size_t)n1 * H2_ + kc2n + q1 * 4);
            pR[1] = *(const uint4*)(Rrow + (size_t)n1 * H2_ + kc2n + q1 * 4);
        }
        #pragma unroll
        for (int kk2 = 0; kk2 < 16; kk2++) {
            const int k0 = kc + 2 * kk2;
            float wA[5], wB[5];
            #pragma unroll
            for (int j = 0; j < 5; j++) {
                wA[j] = sW[k0 * 5 + j];
                wB[j] = sW[(k0 + 1) * 5 + j];
            }
            #pragma unroll
            for (int u = 0; u < 4; u++) {
                u32 sv = sS[es[u] + kk2];
                u32 rv = sR[er[u] + kk2];
                __half2 s2 = *reinterpret_cast<const __half2*>(&sv);
                __half2 r2 = *reinterpret_cast<const __half2*>(&rv);
                __half2 h2 = __hmax2(__hadd2(s2, r2), zero2);
                float2 f = __half22float2(h2);
                #pragma unroll
                for (int j = 0; j < 5; j++)
                    acc[u][j] = fmaf(f.x, wA[j], fmaf(f.y, wB[j], acc[u][j]));
            }
        }
    }

    #pragma unroll
    for (int u = 0; u < 4; u++) {
        size_t o = ((size_t)(b * 255 + t) * E_ + eo[u]) * 5;
        #pragma unroll
        for (int j = 0; j < 5; j++) out[o + j] = acc[u][j] + bb[j];
    }
}

// ---------------------------------------------------------------------------
extern "C" void kernel_launch(void* const* d_in, const int* in_sizes, int n_in,
                              void* d_out, int out_size)
{
    const float* spikes = (const float*)d_in[0];
    const float* W_emb  = (const float*)d_in[1];
    const float* b_emb  = (const float*)d_in[2];
    const float* Ws1    = (const float*)d_in[3];
    const float* bs1    = (const float*)d_in[4];
    const float* Ws2    = (const float*)d_in[5];
    const float* bs2    = (const float*)d_in[6];
    const float* Wr1    = (const float*)d_in[7];
    const float* br1    = (const float*)d_in[8];
    const float* Wr2    = (const float*)d_in[9];
    const float* br2    = (const float*)d_in[10];
    const float* Wc1    = (const float*)d_in[11];
    const float* bc1    = (const float*)d_in[12];
    const float* Wc2    = (const float*)d_in[13];
    const float* bc2    = (const float*)d_in[14];
    const int*   se     = (const int*)d_in[15];
    const int*   re     = (const int*)d_in[16];
    float* out = (float*)d_out;

    aux_prep<<<397, 256>>>(W_emb, Ws1, Ws2, Wr1, Wr2, Wc1, bc1, se, re);

    chain_mma<<<dim3(M_TOTAL / 64, 2), 128>>>(
        spikes, b_emb, bs1, bs2, br1, br2);

    edge_kernel<<<dim3(255, 2), 256>>>(Wc2, bc2, out);
}